// round 1
// baseline (speedup 1.0000x reference)
#include <cuda_runtime.h>
#include <math.h>

// FusionHead fused kernel: B rows x (proj -> 2-token MHA -> FFN -> heads)
// D=192, H=3, HD=64, FFN hidden 384, fingerprint 128.
//
// Output layout (flattened tuple, in order):
//   out[0*B + i]            = sigmoid(logits)[i,0]
//   out[1*B + i]            = sigmoid(logits)[i,1]
//   out[2*B + i]            = sigmoid(logits)[i,2]
//   out[3*B + i*128 + f]    = normalized fingerprint[i,f]

#define D    192
#define HD   64
#define FPD  128
#define RPB  16          // rows per block
#define NT   192         // threads per block (one per feature)
#define RT   32          // row-tokens per block = 2*RPB

// smem layout (floats)
#define OFF_SEQ   0                      // [32][192]  seq -> x (in place)
#define OFF_QKV   (RT * D)               // [32][576]  staging / qkv / ctx / h / heads
#define OFF_SC    (OFF_QKV + RT * 3 * D) // [16][12]   attention scores
#define OFF_MU    (OFF_SC + RPB * 12)    // [32]
#define OFF_RSTD  (OFF_MU + RT)          // [32]
#define OFF_INV   (OFF_RSTD + RT)        // [16]
#define SMEM_FLOATS (OFF_INV + RPB)
#define SMEM_BYTES  (SMEM_FLOATS * 4)

static __device__ __forceinline__ float4 ldf4(const float* p) {
    return *reinterpret_cast<const float4*>(p);
}

// out[r] = dot(wrow[0..K), sin[r*sstride .. +K)) for r in [0,NR)
// Weight row via LDG.128 (1 per 4K FMAs * NR rows), activations via broadcast LDS.128.
template <int NR>
static __device__ __forceinline__ void dotK(
    const float* __restrict__ wrow, int K,
    const float* __restrict__ sin, int sstride,
    float acc[NR])
{
#pragma unroll
    for (int r = 0; r < NR; r++) acc[r] = 0.f;
#pragma unroll 2
    for (int k0 = 0; k0 < K; k0 += 4) {
        const float4 w4 = ldf4(wrow + k0);
#pragma unroll
        for (int r = 0; r < NR; r++) {
            const float4 i4 = ldf4(sin + r * sstride + k0);
            acc[r] = fmaf(w4.x, i4.x, acc[r]);
            acc[r] = fmaf(w4.y, i4.y, acc[r]);
            acc[r] = fmaf(w4.z, i4.z, acc[r]);
            acc[r] = fmaf(w4.w, i4.w, acc[r]);
        }
    }
}

// In-place LayerNorm over last dim (192) for 32 row-tokens in sSeq.
static __device__ __forceinline__ void block_layernorm(
    float* __restrict__ sSeq, float* __restrict__ sMu, float* __restrict__ sRstd,
    const float* __restrict__ g, const float* __restrict__ b, int tid)
{
    const int wid = tid >> 5, lane = tid & 31;
    for (int rt = wid; rt < RT; rt += NT / 32) {
        float s = 0.f, s2 = 0.f;
#pragma unroll
        for (int i = lane; i < D; i += 32) {
            float v = sSeq[rt * D + i];
            s += v;
            s2 = fmaf(v, v, s2);
        }
#pragma unroll
        for (int o = 16; o > 0; o >>= 1) {
            s  += __shfl_xor_sync(0xFFFFFFFFu, s, o);
            s2 += __shfl_xor_sync(0xFFFFFFFFu, s2, o);
        }
        if (lane == 0) {
            float mu  = s * (1.f / D);
            float var = s2 * (1.f / D) - mu * mu;
            sMu[rt]   = mu;
            sRstd[rt] = rsqrtf(var + 1e-5f);
        }
    }
    __syncthreads();
    const float gg = g[tid], bb = b[tid];
#pragma unroll 4
    for (int rt = 0; rt < RT; rt++) {
        float v = sSeq[rt * D + tid];
        sSeq[rt * D + tid] = (v - sMu[rt]) * sRstd[rt] * gg + bb;
    }
    __syncthreads();
}

__global__ void __launch_bounds__(NT, 2)
fusion_head_kernel(
    const float* __restrict__ perc, const float* __restrict__ tech,
    const float* __restrict__ Wp,   const float* __restrict__ bp,
    const float* __restrict__ Wt,   const float* __restrict__ bt,
    const float* __restrict__ in_w, const float* __restrict__ in_b,
    const float* __restrict__ out_w,const float* __restrict__ out_b,
    const float* __restrict__ w1,   const float* __restrict__ b1,
    const float* __restrict__ w2,   const float* __restrict__ b2,
    const float* __restrict__ ln1g, const float* __restrict__ ln1b,
    const float* __restrict__ ln2g, const float* __restrict__ ln2b,
    const float* __restrict__ cw1,  const float* __restrict__ cb1,
    const float* __restrict__ cw2,  const float* __restrict__ cb2,
    const float* __restrict__ fw,   const float* __restrict__ fb,
    float* __restrict__ out, int B)
{
    extern __shared__ float sm[];
    float* sSeq  = sm + OFF_SEQ;   // [32][192] stride 192
    float* sQKV  = sm + OFF_QKV;   // [32][576] stride 576
    float* sSc   = sm + OFF_SC;
    float* sMu   = sm + OFF_MU;
    float* sRstd = sm + OFF_RSTD;
    float* sInv  = sm + OFF_INV;

    const int tid = threadIdx.x;
    const int r0  = blockIdx.x * RPB;

    // ---------- stage perc rows into sQKV rows (stride 576), compute p ----------
#pragma unroll
    for (int r = 0; r < RPB; r++) {
        int gr = r0 + r; if (gr >= B) gr = B - 1;
        sQKV[r * 576 + tid] = perc[(size_t)gr * D + tid];
    }
    __syncthreads();
    {
        float acc[RPB];
        dotK<RPB>(Wp + tid * D, D, sQKV, 576, acc);
        const float bb = bp[tid];
#pragma unroll
        for (int r = 0; r < RPB; r++) sSeq[(2 * r) * D + tid] = acc[r] + bb;
    }
    __syncthreads();

    // ---------- stage tech rows, compute t ----------
#pragma unroll
    for (int r = 0; r < RPB; r++) {
        int gr = r0 + r; if (gr >= B) gr = B - 1;
        sQKV[r * 576 + tid] = tech[(size_t)gr * D + tid];
    }
    __syncthreads();
    {
        float acc[RPB];
        dotK<RPB>(Wt + tid * D, D, sQKV, 576, acc);
        const float bb = bt[tid];
#pragma unroll
        for (int r = 0; r < RPB; r++) sSeq[(2 * r + 1) * D + tid] = acc[r] + bb;
    }
    __syncthreads();

    // ---------- qkv = seq @ in_w^T + in_b  (3 passes: q,k,v) ----------
    for (int m = 0; m < 3; m++) {
        float acc[RT];
        dotK<RT>(in_w + (size_t)(m * D + tid) * D, D, sSeq, D, acc);
        const float bb = in_b[m * D + tid];
#pragma unroll
        for (int rt = 0; rt < RT; rt++) sQKV[rt * 576 + m * D + tid] = acc[rt] + bb;
    }
    __syncthreads();

    // ---------- attention scores: one 64-dot per thread ----------
    {
        const int r   = tid / 12;
        const int idx = tid % 12;
        const int h = idx >> 2, qt = (idx >> 1) & 1, kt = idx & 1;
        const float* q  = &sQKV[(2 * r + qt) * 576 + h * HD];
        const float* kk = &sQKV[(2 * r + kt) * 576 + D + h * HD];
        float s = 0.f;
#pragma unroll
        for (int d = 0; d < HD; d += 4) {
            float4 qa = ldf4(q + d), ka = ldf4(kk + d);
            s = fmaf(qa.x, ka.x, s);
            s = fmaf(qa.y, ka.y, s);
            s = fmaf(qa.z, ka.z, s);
            s = fmaf(qa.w, ka.w, s);
        }
        sSc[tid] = s * 0.125f;   // 1/sqrt(64)
    }
    __syncthreads();

    // ---------- softmax + ctx (overwrites the q slots, cols [0,192)) ----------
    {
        const int h = tid >> 6;  // head of this output dim
#pragma unroll 2
        for (int r = 0; r < RPB; r++) {
            const float v0 = sQKV[(2 * r)     * 576 + 2 * D + tid];
            const float v1 = sQKV[(2 * r + 1) * 576 + 2 * D + tid];
            const float* sc = &sSc[r * 12 + h * 4];
            float ctx0, ctx1;
            {
                float s0 = sc[0], s1 = sc[1];
                float mx = fmaxf(s0, s1);
                float e0 = __expf(s0 - mx), e1 = __expf(s1 - mx);
                ctx0 = (e0 * v0 + e1 * v1) / (e0 + e1);
            }
            {
                float s0 = sc[2], s1 = sc[3];
                float mx = fmaxf(s0, s1);
                float e0 = __expf(s0 - mx), e1 = __expf(s1 - mx);
                ctx1 = (e0 * v0 + e1 * v1) / (e0 + e1);
            }
            sQKV[(2 * r)     * 576 + tid] = ctx0;
            sQKV[(2 * r + 1) * 576 + tid] = ctx1;
        }
    }
    __syncthreads();

    // ---------- attn out-proj, residual-add into sSeq ----------
    {
        float acc[RT];
        dotK<RT>(out_w + (size_t)tid * D, D, sQKV, 576, acc);
        const float bb = out_b[tid];
#pragma unroll
        for (int rt = 0; rt < RT; rt++) sSeq[rt * D + tid] += acc[rt] + bb;
    }
    __syncthreads();

    // ---------- LN1 ----------
    block_layernorm(sSeq, sMu, sRstd, ln1g, ln1b, tid);

    // ---------- FFN1: relu(x @ w1^T + b1) -> sQKV cols [0,384) ----------
    for (int m = 0; m < 2; m++) {
        float acc[RT];
        dotK<RT>(w1 + (size_t)(m * D + tid) * D, D, sSeq, D, acc);
        const float bb = b1[m * D + tid];
#pragma unroll
        for (int rt = 0; rt < RT; rt++)
            sQKV[rt * 576 + m * D + tid] = fmaxf(acc[rt] + bb, 0.f);
    }
    __syncthreads();

    // ---------- FFN2, residual-add into sSeq ----------
    {
        float acc[RT];
        dotK<RT>(w2 + (size_t)tid * 2 * D, 2 * D, sQKV, 576, acc);
        const float bb = b2[tid];
#pragma unroll
        for (int rt = 0; rt < RT; rt++) sSeq[rt * D + tid] += acc[rt] + bb;
    }
    __syncthreads();

    // ---------- LN2 ----------
    block_layernorm(sSeq, sMu, sRstd, ln2g, ln2b, tid);

    // ---------- pooled z into sSeq rows [0,16) (per-column, hazard-free) ----------
#pragma unroll
    for (int r = 0; r < RPB; r++) {
        float z = 0.5f * (sSeq[(2 * r) * D + tid] + sSeq[(2 * r + 1) * D + tid]);
        sSeq[r * D + tid] = z;
    }
    __syncthreads();

    // ---------- classifier hidden -> sQKV rows [0,16); fingerprint -> rows [16,32) ----------
    {
        float acc[RPB];
        dotK<RPB>(cw1 + (size_t)tid * D, D, sSeq, D, acc);
        const float bb = cb1[tid];
#pragma unroll
        for (int r = 0; r < RPB; r++) sQKV[r * 576 + tid] = fmaxf(acc[r] + bb, 0.f);
    }
    if (tid < FPD) {
        float acc[RPB];
        dotK<RPB>(fw + (size_t)tid * D, D, sSeq, D, acc);
        const float bb = fb[tid];
#pragma unroll
        for (int r = 0; r < RPB; r++) sQKV[(RPB + r) * 576 + tid] = acc[r] + bb;
    }
    __syncthreads();

    // ---------- logits + sigmoid ----------
    if (tid < 3 * RPB) {
        const int r = tid / 3, c = tid % 3;
        const float* y = &sQKV[r * 576];
        const float* w = cw2 + c * D;
        float s = cb2[c];
#pragma unroll
        for (int k = 0; k < D; k += 4) {
            float4 ya = ldf4(y + k), wa = ldf4(w + k);
            s = fmaf(ya.x, wa.x, s);
            s = fmaf(ya.y, wa.y, s);
            s = fmaf(ya.z, wa.z, s);
            s = fmaf(ya.w, wa.w, s);
        }
        const int gr = r0 + r;
        if (gr < B) out[(size_t)c * B + gr] = 1.f / (1.f + __expf(-s));
    }

    // ---------- fingerprint norm ----------
    if (tid < RPB) {
        const float* fpv = &sQKV[(RPB + tid) * 576];
        float ss = 0.f;
#pragma unroll 4
        for (int i = 0; i < FPD; i++) ss = fmaf(fpv[i], fpv[i], ss);
        sInv[tid] = 1.f / fmaxf(sqrtf(ss), 1e-12f);
    }
    __syncthreads();
    if (tid < FPD) {
#pragma unroll
        for (int r = 0; r < RPB; r++) {
            const int gr = r0 + r;
            if (gr < B)
                out[(size_t)3 * B + (size_t)gr * FPD + tid] =
                    sQKV[(RPB + r) * 576 + tid] * sInv[r];
        }
    }
}

extern "C" void kernel_launch(void* const* d_in, const int* in_sizes, int n_in,
                              void* d_out, int out_size)
{
    (void)n_in; (void)out_size;
    const float* perc = (const float*)d_in[0];
    const float* tech = (const float*)d_in[1];
    const float* Wp   = (const float*)d_in[2];
    const float* bp   = (const float*)d_in[3];
    const float* Wt   = (const float*)d_in[4];
    const float* bt   = (const float*)d_in[5];
    const float* in_w = (const float*)d_in[6];
    const float* in_b = (const float*)d_in[7];
    const float* outw = (const float*)d_in[8];
    const float* outb = (const float*)d_in[9];
    const float* w1   = (const float*)d_in[10];
    const float* b1   = (const float*)d_in[11];
    const float* w2   = (const float*)d_in[12];
    const float* b2   = (const float*)d_in[13];
    const float* ln1g = (const float*)d_in[14];
    const float* ln1b = (const float*)d_in[15];
    const float* ln2g = (const float*)d_in[16];
    const float* ln2b = (const float*)d_in[17];
    const float* cw1  = (const float*)d_in[18];
    const float* cb1  = (const float*)d_in[19];
    const float* cw2  = (const float*)d_in[20];
    const float* cb2  = (const float*)d_in[21];
    const float* fw   = (const float*)d_in[22];
    const float* fb   = (const float*)d_in[23];

    const int B = in_sizes[0] / D;
    const int grid = (B + RPB - 1) / RPB;

    cudaFuncSetAttribute(fusion_head_kernel,
                         cudaFuncAttributeMaxDynamicSharedMemorySize, SMEM_BYTES);

    fusion_head_kernel<<<grid, NT, SMEM_BYTES>>>(
        perc, tech, Wp, bp, Wt, bt, in_w, in_b, outw, outb,
        w1, b1, w2, b2, ln1g, ln1b, ln2g, ln2b,
        cw1, cb1, cw2, cb2, fw, fb, (float*)d_out, B);
}